// round 9
// baseline (speedup 1.0000x reference)
#include <cuda_runtime.h>
#include <cuda_fp16.h>

#define B    32
#define N    100000
#define DEG  16
#define WPB  10                 // warps per block
#define SPW  8                  // segments per warp
#define SPB  (WPB * SPW)        // 80 segments per block
#define NBLK (N / SPB)          // 1250, exact

// Scratch: transposed x in fp16, shape (N, 32). 6.4 MB static device array.
__device__ __half g_xT[(size_t)N * B];

// Compile-time component select (j is a constant in unrolled loops).
__device__ __forceinline__ int   icomp(const int4& v, int j)   { return j==0?v.x : j==1?v.y : j==2?v.z : v.w; }
__device__ __forceinline__ float fcomp(const float4& v, int j) { return j==0?v.x : j==1?v.y : j==2?v.z : v.w; }

// ---------------------------------------------------------------------------
// Kernel 1: transpose x (B=32, N) fp32 -> x_T (N, 32) fp16.
// 128 threads / 32 columns per block. Loads float4 coalesced, stages in smem,
// writes each 64B xT row with STG.128 (one uint4 per thread).
// ---------------------------------------------------------------------------
__global__ __launch_bounds__(128) void transpose_kernel(const float* __restrict__ x,
                                                        __half* __restrict__ xT) {
    __shared__ __half sh[32][33];          // [batch][col], pad to dodge conflicts
    const int t  = threadIdx.x;
    const int n0 = blockIdx.x * 32;

    // Load: thread t -> batch b = t/4, cols 8*(t%4)..+7 (two float4, coalesced).
    {
        const int b  = t >> 2;
        const int c8 = (t & 3) * 8;
        const float4* p = (const float4*)(x + (size_t)b * N + n0 + c8);
        float4 v0 = __ldcg(&p[0]);
        float4 v1 = __ldcg(&p[1]);
        sh[b][c8 + 0] = __float2half_rn(v0.x);
        sh[b][c8 + 1] = __float2half_rn(v0.y);
        sh[b][c8 + 2] = __float2half_rn(v0.z);
        sh[b][c8 + 3] = __float2half_rn(v0.w);
        sh[b][c8 + 4] = __float2half_rn(v1.x);
        sh[b][c8 + 5] = __float2half_rn(v1.y);
        sh[b][c8 + 6] = __float2half_rn(v1.z);
        sh[b][c8 + 7] = __float2half_rn(v1.w);
    }
    __syncthreads();

    // Store: thread t -> row n = n0 + t/4, batch octet q = t%4 (STG.128).
    {
        const int col = t >> 2;
        const int q   = t & 3;
        unsigned u[4];
        #pragma unroll
        for (int j = 0; j < 4; j++) {
            unsigned lo = __half_as_ushort(sh[8 * q + 2 * j + 0][col]);
            unsigned hi = __half_as_ushort(sh[8 * q + 2 * j + 1][col]);
            u[j] = lo | (hi << 16);
        }
        uint4 wv = make_uint4(u[0], u[1], u[2], u[3]);
        *(uint4*)(xT + (size_t)(n0 + col) * B + 8 * q) = wv;
    }
}

// ---------------------------------------------------------------------------
// Kernel 2: one warp handles EIGHT segments.
//   o = lane/4 owns segment segW + o; r = lane%4 handles batches 8r..8r+7.
//   Each gather is one LDG.128 (uint4 = 8 fp16) serving all 8 segments.
// Edge data loaded warp-cooperatively (1 LDG.128/lane for src/kern/bias,
// fully coalesced), redistributed via quad-local shuffles.
// fp32 accumulation; smem transpose; float4 coalesced write-out.
// ---------------------------------------------------------------------------
__global__ __launch_bounds__(320, 3) void pc_kernel(const float* __restrict__ kern,
                                                    const float* __restrict__ bias,
                                                    const int*   __restrict__ edge_src,
                                                    const __half* __restrict__ xT,
                                                    float*       __restrict__ out) {
    __shared__ float s_out[SPB][33];

    const int t    = threadIdx.x;
    const int warp = t >> 5;
    const int lane = t & 31;
    const int o    = lane >> 2;            // segment within warp (0..7)
    const int r    = lane & 3;             // batch-octet index (0..3)
    const unsigned qbase = lane & ~3u;     // first lane of my quad

    const int    segW = blockIdx.x * SPB + warp * SPW;
    const size_t eW   = (size_t)segW * DEG;     // 128 edges, 64B aligned

    // Warp-cooperative edge loads: lane l holds edges 4l..4l+3 (= segment l/4,
    // local d = 4*(l%4) .. +3). Fully coalesced, 512B each.
    int4   sv = __ldcg(&((const int4*)  (edge_src + eW))[lane]);
    float4 kv = __ldcg(&((const float4*)(kern     + eW))[lane]);
    float4 bv = __ldcg(&((const float4*)(bias     + eW))[lane]);

    // Bias sum for my segment: reduce over my quad (lanes qbase..qbase+3).
    float lb = bv.x + bv.y + bv.z + bv.w;
    lb += __shfl_xor_sync(0xffffffffu, lb, 1);
    lb += __shfl_xor_sync(0xffffffffu, lb, 2);

    // Redistribute src indices: s[d] = src of edge (my segment)*16 + d.
    int s[16];
    #pragma unroll
    for (int d = 0; d < 16; d++)
        s[d] = __shfl_sync(0xffffffffu, icomp(sv, d & 3), qbase + (d >> 2));

    const uint4* xr = (const uint4*)xT;    // xT row = 4 x uint4 (64B)

    float a[8];
    #pragma unroll
    for (int j = 0; j < 8; j++) a[j] = lb;

    // FMA for one gather group element: g = 8 fp16 batch values, weight kd.
    auto fma8 = [&](uint4 g, float kd) {
        float2 f0 = __half22float2(*(const __half2*)&g.x);
        float2 f1 = __half22float2(*(const __half2*)&g.y);
        float2 f2 = __half22float2(*(const __half2*)&g.z);
        float2 f3 = __half22float2(*(const __half2*)&g.w);
        a[0] = fmaf(f0.x, kd, a[0]);  a[1] = fmaf(f0.y, kd, a[1]);
        a[2] = fmaf(f1.x, kd, a[2]);  a[3] = fmaf(f1.y, kd, a[3]);
        a[4] = fmaf(f2.x, kd, a[4]);  a[5] = fmaf(f2.y, kd, a[5]);
        a[6] = fmaf(f3.x, kd, a[6]);  a[7] = fmaf(f3.y, kd, a[7]);
    };

    // Ping-pong gather groups of 4 (peak 8 uint4 = 32 regs in flight).
    uint4 gA[4], gB[4];
    #pragma unroll
    for (int d = 0; d < 4; d++) gA[d] = __ldcg(&xr[(size_t)s[d] * 4 + r]);
    #pragma unroll
    for (int d = 0; d < 4; d++) gB[d] = __ldcg(&xr[(size_t)s[4 + d] * 4 + r]);

    #pragma unroll
    for (int d = 0; d < 4; d++) {
        float kd = __shfl_sync(0xffffffffu, fcomp(kv, d & 3), qbase + (d >> 2));
        fma8(gA[d], kd);
    }
    #pragma unroll
    for (int d = 0; d < 4; d++) gA[d] = __ldcg(&xr[(size_t)s[8 + d] * 4 + r]);

    #pragma unroll
    for (int d = 4; d < 8; d++) {
        float kd = __shfl_sync(0xffffffffu, fcomp(kv, d & 3), qbase + (d >> 2));
        fma8(gB[d - 4], kd);
    }
    #pragma unroll
    for (int d = 0; d < 4; d++) gB[d] = __ldcg(&xr[(size_t)s[12 + d] * 4 + r]);

    #pragma unroll
    for (int d = 8; d < 12; d++) {
        float kd = __shfl_sync(0xffffffffu, fcomp(kv, d & 3), qbase + (d >> 2));
        fma8(gA[d - 8], kd);
    }
    #pragma unroll
    for (int d = 12; d < 16; d++) {
        float kd = __shfl_sync(0xffffffffu, fcomp(kv, d & 3), qbase + (d >> 2));
        fma8(gB[d - 12], kd);
    }

    // Stage: s_out[seg][8r+j]. Banks (33*seg + 8r + j) mod 32 conflict-free per j.
    const int seg = warp * SPW + o;
    #pragma unroll
    for (int j = 0; j < 8; j++) s_out[seg][8 * r + j] = a[j];
    __syncthreads();

    // Write-out: thread t -> batch b = t/10, segment group c = t%10.
    // out[b][n0 + 8c .. 8c+7] via two float4; coalesced per batch row.
    const int b  = t / WPB;
    const int c  = t % WPB;
    const int n0 = blockIdx.x * SPB;
    float4 v0 = make_float4(s_out[8 * c + 0][b], s_out[8 * c + 1][b],
                            s_out[8 * c + 2][b], s_out[8 * c + 3][b]);
    float4 v1 = make_float4(s_out[8 * c + 4][b], s_out[8 * c + 5][b],
                            s_out[8 * c + 6][b], s_out[8 * c + 7][b]);
    float* dst = out + (size_t)b * N + n0 + 8 * c;
    *(float4*)(dst)     = v0;
    *(float4*)(dst + 4) = v1;
}

// ---------------------------------------------------------------------------
// d_in order: x, kernel, bias, edge_src, segment_ids, num_units
// ---------------------------------------------------------------------------
extern "C" void kernel_launch(void* const* d_in, const int* in_sizes, int n_in,
                              void* d_out, int out_size) {
    const float* x        = (const float*)d_in[0];
    const float* kern     = (const float*)d_in[1];
    const float* bias     = (const float*)d_in[2];
    const int*   edge_src = (const int*)  d_in[3];
    float*       out      = (float*)d_out;

    __half* xT;
    cudaGetSymbolAddress((void**)&xT, g_xT);

    transpose_kernel<<<N / 32, 128>>>(x, xT);
    pc_kernel<<<NBLK, WPB * 32>>>(kern, bias, edge_src, xT, out);
}

// round 11
// speedup vs baseline: 1.2034x; 1.2034x over previous
#include <cuda_runtime.h>
#include <cuda_fp16.h>

#define B    32
#define N    100000
#define DEG  16
#define SPB  32                  // segments per block (8 warps x 4 segs/warp)
#define NBLK (N / SPB)           // 3125, exact

// Scratch: transposed x in fp16, shape (N, 32). 6.4 MB static device array.
__device__ __half g_xT[(size_t)N * B];

__device__ __forceinline__ unsigned ucomp(const uint4& v, int j) {
    return j == 0 ? v.x : j == 1 ? v.y : j == 2 ? v.z : v.w;
}

// ---------------------------------------------------------------------------
// Kernel 1: transpose x (B=32, N) fp32 -> x_T (N, 32) fp16.
// Round-7 load phase (proven); vectorized store: each thread packs 4 halves
// and writes one uint2; warp writes 256B contiguous. Conflict-free banks.
// ---------------------------------------------------------------------------
__global__ __launch_bounds__(256) void transpose_kernel(const float* __restrict__ x,
                                                        __half* __restrict__ xT) {
    __shared__ float tile[32][33];
    const int t  = threadIdx.x;
    const int tx = t & 31;
    const int ty = t >> 5;            // 0..7
    const int n0 = blockIdx.x * 32;

    #pragma unroll
    for (int k = 0; k < 4; k++) {
        int b = ty + k * 8;
        tile[b][tx] = x[(size_t)b * N + n0 + tx];
    }
    __syncthreads();

    // Store: thread t -> xT row col = t/8, batch quad q = t%8 (8B uint2).
    // Banks: (4q+j)*33 + col -> 4q + j + col mod 32, distinct per j.
    {
        const int col = t >> 3;
        const int q   = t & 7;
        __half2 h0 = __floats2half2_rn(tile[4 * q + 0][col], tile[4 * q + 1][col]);
        __half2 h1 = __floats2half2_rn(tile[4 * q + 2][col], tile[4 * q + 3][col]);
        uint2 w = make_uint2(*reinterpret_cast<unsigned*>(&h0),
                             *reinterpret_cast<unsigned*>(&h1));
        *(uint2*)(xT + (size_t)(n0 + col) * B + 4 * q) = w;
    }
}

// ---------------------------------------------------------------------------
// Kernel 2: one warp handles FOUR segments (round-7 layout).
//   q = lane/8 owns segment; r = lane%8 handles batches 4r..4r+3 (uint2 gather).
// Uniform edge data loaded cooperatively in 2 LDG.128s
//   ld1: lanes 0-15 -> src int4 chunks (seg h/4, chunk h%4)
//        lanes 16-31 -> kern float4 chunks (same indexing, h-16)
//   ldb: all lanes -> bias chunk (lane&15)
// then redistributed via warp shuffles (ALU pipe has headroom).
// ---------------------------------------------------------------------------
__global__ __launch_bounds__(256) void pc_kernel(const float* __restrict__ kern,
                                                 const float* __restrict__ bias,
                                                 const int*   __restrict__ edge_src,
                                                 const __half* __restrict__ xT,
                                                 float*       __restrict__ out) {
    __shared__ float s_out[SPB][33];

    const int t    = threadIdx.x;
    const int warp = t >> 5;
    const int lane = t & 31;
    const int q    = lane >> 3;             // 0..3 : segment within warp
    const int r    = lane & 7;              // 0..7 : batch-quad index

    const int seg_in_blk = (warp << 2) | q; // 0..31
    const int segW = blockIdx.x * SPB + (warp << 2);
    const size_t eW = (size_t)segW * DEG;   // warp's 64 edges, 256B aligned

    // Cooperative uniform loads: 2 instructions replace 12 broadcasts.
    const uint4*  pSrc = (const uint4*) (edge_src + eW);   // 16 x int4
    const uint4*  pK   = (const uint4*) (kern + eW);       // 16 x float4
    const float4* pB   = (const float4*)(bias + eW);

    uint4  ld1 = __ldcg(lane < 16 ? &pSrc[lane] : &pK[lane - 16]);
    float4 bv  = __ldcg(&pB[lane & 15]);

    // Bias: per-chunk partial sum, gather my segment's 4 chunks via shfl.
    float psum = (bv.x + bv.y) + (bv.z + bv.w);
    float bsum = 0.0f;
    #pragma unroll
    for (int j = 0; j < 4; j++)
        bsum += __shfl_sync(0xffffffffu, psum, (q << 2) + j);

    // Src indices: 16 shfls from lanes q*4..q*4+3 (which hold src chunks).
    int s[16];
    #pragma unroll
    for (int j = 0; j < 4; j++) {
        const int hl = (q << 2) + j;
        s[4 * j + 0] = (int)__shfl_sync(0xffffffffu, ld1.x, hl);
        s[4 * j + 1] = (int)__shfl_sync(0xffffffffu, ld1.y, hl);
        s[4 * j + 2] = (int)__shfl_sync(0xffffffffu, ld1.z, hl);
        s[4 * j + 3] = (int)__shfl_sync(0xffffffffu, ld1.w, hl);
    }

    // 16 gathers, each uint2 = 4 fp16 batch elements; L2-only.
    const uint2* xt4 = (const uint2*)xT;    // xT row = 8 x uint2 (64B)
    uint2 g[16];
    #pragma unroll
    for (int d = 0; d < 16; d++)
        g[d] = __ldcg(&xt4[(size_t)s[d] * 8 + r]);

    // FMA loop; k[d] pulled by shfl from lanes 16 + q*4 + d/4 (kern holders).
    float a0 = bsum, a1 = bsum, a2 = bsum, a3 = bsum;
    #pragma unroll
    for (int d = 0; d < 16; d++) {
        unsigned kb = __shfl_sync(0xffffffffu, ucomp(ld1, d & 3),
                                  16 + (q << 2) + (d >> 2));
        float kd = __uint_as_float(kb);
        float2 lo = __half22float2(*(const __half2*)&g[d].x);
        float2 hi = __half22float2(*(const __half2*)&g[d].y);
        a0 = fmaf(lo.x, kd, a0);
        a1 = fmaf(lo.y, kd, a1);
        a2 = fmaf(hi.x, kd, a2);
        a3 = fmaf(hi.y, kd, a3);
    }

    // Stage: s_out[seg][4r..4r+3]; banks (33*seg + 4r + j) mod 32 distinct per j.
    s_out[seg_in_blk][4 * r + 0] = a0;
    s_out[seg_in_blk][4 * r + 1] = a1;
    s_out[seg_in_blk][4 * r + 2] = a2;
    s_out[seg_in_blk][4 * r + 3] = a3;
    __syncthreads();

    // Write-out: thread t -> batch row b = t/8, float4 column c = t%8.
    // out[b][n0 + 4c .. 4c+3]; 128B contiguous per batch row per block.
    const int b  = t >> 3;
    const int c  = t & 7;
    const int n0 = blockIdx.x * SPB;
    float4 v = make_float4(s_out[4 * c + 0][b], s_out[4 * c + 1][b],
                           s_out[4 * c + 2][b], s_out[4 * c + 3][b]);
    *(float4*)(out + (size_t)b * N + n0 + 4 * c) = v;
}

// ---------------------------------------------------------------------------
// d_in order: x, kernel, bias, edge_src, segment_ids, num_units
// ---------------------------------------------------------------------------
extern "C" void kernel_launch(void* const* d_in, const int* in_sizes, int n_in,
                              void* d_out, int out_size) {
    const float* x        = (const float*)d_in[0];
    const float* kern     = (const float*)d_in[1];
    const float* bias     = (const float*)d_in[2];
    const int*   edge_src = (const int*)  d_in[3];
    float*       out      = (float*)d_out;

    __half* xT;
    cudaGetSymbolAddress((void**)&xT, g_xT);

    transpose_kernel<<<N / 32, 256>>>(x, xT);
    pc_kernel<<<NBLK, 256>>>(kern, bias, edge_src, xT, out);
}